// round 7
// baseline (speedup 1.0000x reference)
#include <cuda_runtime.h>
#include <cstdint>

// KA_BSpline_Core: out[n] = b_out + sum_q a[q] * spline_q( sigmoid(2*scale*(emb[n]·W[q]+b_inner[q])) )
//
// R6: persistent CTAs (592 = 4/SM), grid-stride over 256-point tiles, with the
// double-buffered cp.async chunk pipeline running CONTINUOUSLY across tile
// boundaries (last chunk of tile T issues chunk 0 of tile T+stride). This
// removes the per-tile prologue/epilogue DRAM bubbles and wave transitions
// that capped R4/R5 at DRAM=63%. Warp-synchronous handshake (no block
// barriers in the mainloop), XOR-swizzled smem, packed fma.rn.f32x2 GEMV.

#define QDIM   12
#define KDIM   256
#define NCTRL  25
#define BLOCK  128
#define TILE   256           // points per tile (2 per thread)
#define KCH    16
#define NCHUNK (KDIM / KCH)  // 16
#define BUF_FLOATS (TILE * KCH)                  // 4096
#define SMEM_FLOATS (2*BUF_FLOATS + QDIM*KDIM + QDIM*NCTRL + 32)
#define SMEM_BYTES  (SMEM_FLOATS * 4)
#define MAXCTA (148 * 4)

__device__ __forceinline__ unsigned long long fma2(unsigned long long a,
                                                   unsigned long long b,
                                                   unsigned long long c) {
    unsigned long long d;
    asm("fma.rn.f32x2 %0, %1, %2, %3;" : "=l"(d) : "l"(a), "l"(b), "l"(c));
    return d;
}

// knots: [0,0,0,0, 1/22 .. 21/22, 1,1,1,1]  -> knot(t) for t in [0,28]
__device__ __forceinline__ float knotv(int t) {
    t -= 3;
    t = t < 0 ? 0 : (t > 22 ? 22 : t);
    return (float)t * (1.0f / 22.0f);
}

__global__ __launch_bounds__(BLOCK, 4)
void kan_bspline_kernel(const float* __restrict__ emb,
                        const float* __restrict__ W,
                        const float* __restrict__ b_inner,
                        const float* __restrict__ inner_scale,
                        const float* __restrict__ coeffs,
                        const float* __restrict__ a_out,
                        const float* __restrict__ b_out,
                        float* __restrict__ out,
                        int npts) {
    extern __shared__ float sh[];
    float* bufs = sh;                          // 2 * BUF_FLOATS
    float* Wsh  = sh + 2 * BUF_FLOATS;         // QDIM*KDIM = 3072
    float* Csh  = Wsh + QDIM * KDIM;           // QDIM*NCTRL = 300
    float* Msh  = Csh + QDIM * NCTRL;          // [0..11]=b_inner [12..23]=a [24]=scale [25]=b_out

    const int tid  = threadIdx.x;
    const int wid  = tid >> 5;                 // warp 0..3
    const int lane = tid & 31;
    const int ntiles = (npts + TILE - 1) / TILE;

    // ---- warp-private cp.async loader ----
    // Warp w loads exactly the rows its own lanes consume:
    //   rows w*32 .. w*32+31  (point base+tid, acc0) and +128 (acc1).
    // XOR swizzle slot = ccol ^ ((row>>1)&3): conflict-free fill & read.
    const int ccol  = lane & 3;
    const int rsub  = lane >> 2;               // 0..7
    const int rbase = wid * 32 + rsub;

    auto issue = [&](int tile, int kc, int b) {
        float* bb = bufs + b * BUF_FLOATS;
        const long long tile0 = (long long)tile * TILE;
        const float* g0 = emb + kc * KCH + ccol * 4;
        if (tile0 + TILE <= (long long)npts) {
#pragma unroll
            for (int h = 0; h < 2; h++) {
#pragma unroll
                for (int i = 0; i < 4; i++) {
                    int row = h * 128 + rbase + 8 * i;
                    int slot = ccol ^ ((row >> 1) & 3);
                    unsigned sa = (unsigned)__cvta_generic_to_shared(bb + row * KCH + slot * 4);
                    asm volatile("cp.async.cg.shared.global [%0], [%1], 16;\n"
                                 :: "r"(sa), "l"(g0 + (tile0 + row) * KDIM));
                }
            }
        } else {
#pragma unroll
            for (int h = 0; h < 2; h++) {
#pragma unroll
                for (int i = 0; i < 4; i++) {
                    int row = h * 128 + rbase + 8 * i;
                    long long prow = tile0 + row;
                    int ok = (prow < (long long)npts);
                    const float* gp = ok ? (g0 + prow * KDIM) : emb;
                    int sz = ok ? 16 : 0;
                    int slot = ccol ^ ((row >> 1) & 3);
                    unsigned sa = (unsigned)__cvta_generic_to_shared(bb + row * KCH + slot * 4);
                    asm volatile("cp.async.cg.shared.global [%0], [%1], 16, %2;\n"
                                 :: "r"(sa), "l"(gp), "r"(sz));
                }
            }
        }
        asm volatile("cp.async.commit_group;\n" ::: "memory");
    };

    // Kick off the very first chunk before staging constants (overlap).
    int tile = blockIdx.x;
    if (tile < ntiles) issue(tile, 0, 0);

    // ---- stage constants into smem (once per CTA lifetime) ----
    for (int i = tid; i < QDIM * KDIM / 4; i += BLOCK)
        ((float4*)Wsh)[i] = ((const float4*)W)[i];
    for (int i = tid; i < QDIM * NCTRL; i += BLOCK)
        Csh[i] = coeffs[i];
    if (tid < QDIM) { Msh[tid] = b_inner[tid]; Msh[12 + tid] = a_out[tid]; }
    if (tid == 0)   { Msh[24] = inner_scale[0]; Msh[25] = b_out[0]; }
    __syncthreads();   // the only block barrier

    const int sw   = (tid >> 1) & 3;  // read-side swizzle (same for row tid and tid+128)
    const int step = gridDim.x;
    const float is = Msh[24];
    int gchunk = 0;                   // global chunk counter -> buffer parity

#pragma unroll 1
    for (; tile < ntiles; tile += step) {
        const long long tile0 = (long long)tile * TILE;

        unsigned long long acc0[QDIM], acc1[QDIM];
#pragma unroll
        for (int q = 0; q < QDIM; q++) { acc0[q] = 0ULL; acc1[q] = 0ULL; }

#pragma unroll 1
        for (int c = 0; c < NCHUNK; c++) {
            // Issue the next chunk: same tile, or chunk 0 of this CTA's next tile.
            if (c + 1 < NCHUNK) {
                issue(tile, c + 1, (gchunk + 1) & 1);
                asm volatile("cp.async.wait_group 1;\n" ::: "memory");
            } else if (tile + step < ntiles) {
                issue(tile + step, 0, (gchunk + 1) & 1);
                asm volatile("cp.async.wait_group 1;\n" ::: "memory");
            } else {
                asm volatile("cp.async.wait_group 0;\n" ::: "memory");
            }
            __syncwarp();

            const float* row0 = bufs + (gchunk & 1) * BUF_FLOATS + tid * KCH;
            const float* row1 = row0 + BLOCK * KCH;     // point tid + 128
            const float* wb   = Wsh + c * KCH;
#pragma unroll
            for (int k4 = 0; k4 < KCH / 4; k4++) {
                const int slot = (k4 ^ sw) * 4;
                ulonglong2 x0 = *(const ulonglong2*)(row0 + slot);
                ulonglong2 x1 = *(const ulonglong2*)(row1 + slot);
#pragma unroll
                for (int q = 0; q < QDIM; q++) {
                    ulonglong2 w = *(const ulonglong2*)(wb + q * KDIM + k4 * 4);
                    acc0[q] = fma2(x0.x, w.x, acc0[q]);
                    acc0[q] = fma2(x0.y, w.y, acc0[q]);
                    acc1[q] = fma2(x1.x, w.x, acc1[q]);
                    acc1[q] = fma2(x1.y, w.y, acc1[q]);
                }
            }
            __syncwarp();
            gchunk++;
        }

        // ---- epilogue: sigmoid + cubic B-spline (de Boor) for both points ----
        // (next tile's chunk 0 is streaming via cp.async while this runs)
#pragma unroll
        for (int pp = 0; pp < 2; pp++) {
            long long myp = tile0 + tid + pp * BLOCK;
            if (myp >= (long long)npts) break;
            const unsigned long long* acc = pp ? acc1 : acc0;
            float res = Msh[25];
#pragma unroll
            for (int q = 0; q < QDIM; q++) {
                float lo, hi;
                asm("mov.b64 {%0, %1}, %2;" : "=f"(lo), "=f"(hi) : "l"(acc[q]));
                float u = lo + hi + Msh[q];
                // s = 0.5*(tanh(is*u)+1) = 1/(1+exp(-2*is*u))
                float e = __expf(-2.0f * is * u);
                float s = __fdividef(1.0f, 1.0f + e);

                int j = (int)(s * 22.0f);
                j = j < 0 ? 0 : (j > 21 ? 21 : j);
                const int i = j + 3;   // knot span: knots[i] <= s < knots[i+1]

                float Nb[4], lft[4], rgt[4];
                Nb[0] = 1.0f;
#pragma unroll
                for (int p = 1; p <= 3; p++) {
                    lft[p] = s - knotv(i + 1 - p);
                    rgt[p] = knotv(i + p) - s;
                    float saved = 0.0f;
#pragma unroll
                    for (int r = 0; r < p; r++) {
                        float den = rgt[r + 1] + lft[p - r];
                        float tmp = __fdividef(Nb[r], den);
                        Nb[r] = fmaf(rgt[r + 1], tmp, saved);
                        saved = lft[p - r] * tmp;
                    }
                    Nb[p] = saved;
                }
                const float* cq = Csh + q * NCTRL + j;   // coeff index (i-3)..i
                float phi = Nb[0] * cq[0] + Nb[1] * cq[1] + Nb[2] * cq[2] + Nb[3] * cq[3];
                res = fmaf(Msh[12 + q], phi, res);
            }
            out[myp] = res;
        }
    }
}

extern "C" void kernel_launch(void* const* d_in, const int* in_sizes, int n_in,
                              void* d_out, int out_size) {
    const float* emb         = (const float*)d_in[0];
    const float* W           = (const float*)d_in[1];
    const float* b_inner     = (const float*)d_in[2];
    const float* inner_scale = (const float*)d_in[3];
    const float* coeffs      = (const float*)d_in[4];
    const float* a           = (const float*)d_in[5];
    const float* b_out       = (const float*)d_in[6];
    float* out = (float*)d_out;

    int npts = out_size;   // (N_POINTS, 1) float32
    int ntiles = (npts + TILE - 1) / TILE;
    int blocks = ntiles < MAXCTA ? ntiles : MAXCTA;

    cudaFuncSetAttribute(kan_bspline_kernel,
                         cudaFuncAttributeMaxDynamicSharedMemorySize, SMEM_BYTES);
    kan_bspline_kernel<<<blocks, BLOCK, SMEM_BYTES>>>(
        emb, W, b_inner, inner_scale, coeffs, a, b_out, out, npts);
}